// round 1
// baseline (speedup 1.0000x reference)
#include <cuda_runtime.h>
#include <cuda_bf16.h>
#include <math.h>

// Problem constants (fixed shapes per reference)
#define D   256
#define DL  256
#define S   2048
#define B   8
#define F   8192
#define NE  (B * F)        // 65536 edges
#define K1  (3 * D)        // 768  (concat input)
#define H1  (2 * D)        // 512  (hidden)
#define TE  32             // edges per tile in edge_mlp

// -------- device scratch (no allocations allowed) --------
__device__ float g_agg[B * S * D];     // 16 MB accumulator
__device__ float g_pooled[B * D];      // pooled sums
__device__ int   g_items[2 * NE];      // compacted (edge,dir) work items
__device__ int   g_count;

__device__ __forceinline__ float gelu_exact(float x) {
    // exact GELU: x * Phi(x)
    return x * normcdff(x);
}

// -------- kernel 1: zero scratch --------
__global__ void zero_kernel() {
    int i = blockIdx.x * blockDim.x + threadIdx.x;
    if (i < B * S * D) g_agg[i] = 0.0f;
    if (i < B * D)     g_pooled[i] = 0.0f;
    if (i == 0)        g_count = 0;
}

// -------- kernel 2: compact work items --------
// fwd item for every valid edge; rev item when valid & !role & add_rev
__global__ void compact_kernel(const int* __restrict__ mask,
                               const int* __restrict__ is_role,
                               const int* __restrict__ add_rev) {
    int e = blockIdx.x * blockDim.x + threadIdx.x;
    if (e >= NE) return;
    if (!mask[e]) return;
    bool rev = (!is_role[e]) && add_rev[e];
    int slot = atomicAdd(&g_count, rev ? 2 : 1);
    g_items[slot] = e << 1;                  // fwd
    if (rev) g_items[slot + 1] = (e << 1) | 1;  // rev
}

// -------- kernel 3: edge MLP + scatter --------
// One CTA handles TE work items: gather X[TE][768] into smem,
// layer1 (768->512) + exact gelu, layer2 (512->256), atomic scatter.
__global__ __launch_bounds__(256) void edge_mlp_kernel(
    const float* __restrict__ pos,   // pos_emb (nodes = first S rows)
    const float* __restrict__ pred,  // pred_emb
    const float* __restrict__ role,  // role_emb
    const float* __restrict__ w1, const float* __restrict__ b1,
    const float* __restrict__ w2, const float* __restrict__ b2,
    const int* __restrict__ pred_idx,
    const int* __restrict__ a0, const int* __restrict__ a1,
    const int* __restrict__ role_idx, const int* __restrict__ is_role)
{
    extern __shared__ float sm[];            // TE*K1 floats (X), reused as H (TE*H1)
    __shared__ const float* srcp[TE][3];
    __shared__ int stgt[TE];                 // (b*S + tgt)*D

    int t = threadIdx.x;                     // 256 threads
    int base = blockIdx.x * TE;
    int count = g_count;
    if (base >= count) return;
    int nE = min(TE, count - base);

    if (t < nE) {
        int item = g_items[base + t];
        int e   = item >> 1;
        int dir = item & 1;
        int b   = e >> 13;                   // F = 8192 = 2^13
        int i0 = a0[e], i1 = a1[e];
        int pi = pred_idx[e];
        const float* s0;
        const float* s2;
        int tg;
        if (dir == 0) {
            int r = is_role[e];
            s0 = pos + (size_t)i0 * D;
            s2 = r ? (role + (size_t)role_idx[e] * D) : (pos + (size_t)i1 * D);
            tg = r ? i0 : i1;
        } else {
            s0 = pos + (size_t)i1 * D;
            s2 = pos + (size_t)i0 * D;
            tg = i0;
        }
        srcp[t][0] = s0;
        srcp[t][1] = pred + (size_t)pi * D;
        srcp[t][2] = s2;
        stgt[t] = (b * S + tg) * D;
    }
    __syncthreads();

    // gather: 3 segments of 256 floats per edge, coalesced
    for (int e = 0; e < nE; e++) {
        sm[e * K1 +       t] = srcp[e][0][t];
        sm[e * K1 + 256 + t] = srcp[e][1][t];
        sm[e * K1 + 512 + t] = srcp[e][2][t];
    }
    __syncthreads();

    // ---- layer 1: H[e][j] = gelu(sum_k X[e][k] * w1[k][j] + b1[j]) ----
    // thread t owns j = 2t, 2t+1 for all TE edges
    float acc0[TE], acc1[TE];
    #pragma unroll
    for (int e = 0; e < TE; e++) { acc0[e] = 0.0f; acc1[e] = 0.0f; }

    const float2* w1v = (const float2*)w1;   // row k = 256 float2
    #pragma unroll 2
    for (int k = 0; k < K1; k++) {
        float2 w = __ldg(&w1v[(size_t)k * 256 + t]);
        #pragma unroll
        for (int e = 0; e < TE; e++) {
            float x = sm[e * K1 + k];        // broadcast
            acc0[e] = fmaf(x, w.x, acc0[e]);
            acc1[e] = fmaf(x, w.y, acc1[e]);
        }
    }
    float2 bj = ((const float2*)b1)[t];
    __syncthreads();                          // done reading X; reuse smem for H

    float2* Hs2 = (float2*)sm;                // row e = 256 float2
    #pragma unroll
    for (int e = 0; e < TE; e++) {
        float2 h;
        h.x = gelu_exact(acc0[e] + bj.x);
        h.y = gelu_exact(acc1[e] + bj.y);
        Hs2[e * 256 + t] = h;
    }
    __syncthreads();

    // ---- layer 2: msg[e][d] = sum_k H[e][k] * w2[k][d] + b2[d], d = t ----
    float acc2[TE];
    #pragma unroll
    for (int e = 0; e < TE; e++) acc2[e] = 0.0f;

    const float* Hs = sm;
    #pragma unroll 2
    for (int k = 0; k < H1; k++) {
        float w = __ldg(&w2[(size_t)k * D + t]);
        #pragma unroll
        for (int e = 0; e < TE; e++) {
            acc2[e] = fmaf(Hs[e * H1 + k], w, acc2[e]);
        }
    }
    float bb = b2[t];
    for (int e = 0; e < nE; e++) {
        atomicAdd(&g_agg[stgt[e] + t], acc2[e] + bb);
    }
}

// -------- kernel 4: x = nodes + agg, layernorm, pooled mean --------
// grid (S/32, B), 256 threads; warp per row, 4 rows per warp
__global__ void norm_pool_kernel(const float* __restrict__ pos,
                                 const float* __restrict__ ln_g,
                                 const float* __restrict__ ln_b)
{
    int b = blockIdx.y;
    int s_base = blockIdx.x * 32;
    int warp = threadIdx.x >> 5;
    int lane = threadIdx.x & 31;

    float gg[8], be[8], pacc[8];
    #pragma unroll
    for (int i = 0; i < 8; i++) {
        gg[i] = ln_g[i * 32 + lane];
        be[i] = ln_b[i * 32 + lane];
        pacc[i] = 0.0f;
    }

    for (int r = warp; r < 32; r += 8) {
        int s = s_base + r;
        const float* ag = &g_agg[((size_t)b * S + s) * D];
        const float* ps = &pos[(size_t)s * D];
        float x[8];
        float sum = 0.0f;
        #pragma unroll
        for (int i = 0; i < 8; i++) {
            x[i] = ps[i * 32 + lane] + ag[i * 32 + lane];
            sum += x[i];
        }
        #pragma unroll
        for (int off = 16; off > 0; off >>= 1)
            sum += __shfl_xor_sync(0xFFFFFFFFu, sum, off);
        float mu = sum * (1.0f / D);
        float v = 0.0f;
        #pragma unroll
        for (int i = 0; i < 8; i++) { x[i] -= mu; v += x[i] * x[i]; }
        #pragma unroll
        for (int off = 16; off > 0; off >>= 1)
            v += __shfl_xor_sync(0xFFFFFFFFu, v, off);
        float inv = rsqrtf(v * (1.0f / D) + 1e-5f);
        #pragma unroll
        for (int i = 0; i < 8; i++)
            pacc[i] += x[i] * inv * gg[i] + be[i];
    }

    __shared__ float sp[256];
    sp[threadIdx.x] = 0.0f;
    __syncthreads();
    #pragma unroll
    for (int i = 0; i < 8; i++)
        atomicAdd(&sp[i * 32 + lane], pacc[i]);
    __syncthreads();
    int t = threadIdx.x;
    atomicAdd(&g_pooled[b * D + t], sp[t] * (1.0f / S));
}

// -------- kernel 5: final small MLP --------
__global__ void final_kernel(const float* __restrict__ lw1, const float* __restrict__ lb1,
                             const float* __restrict__ lw2, const float* __restrict__ lb2,
                             float* __restrict__ out)
{
    __shared__ float P[B * D];
    __shared__ float Hh[B * DL];
    int t = threadIdx.x;  // 256
    for (int i = t; i < B * D; i += 256) P[i] = g_pooled[i];
    __syncthreads();

    float a[B];
    #pragma unroll
    for (int b = 0; b < B; b++) a[b] = lb1[t];
    for (int k = 0; k < D; k++) {
        float w = lw1[k * DL + t];
        #pragma unroll
        for (int b = 0; b < B; b++) a[b] = fmaf(P[b * D + k], w, a[b]);
    }
    #pragma unroll
    for (int b = 0; b < B; b++) Hh[b * DL + t] = gelu_exact(a[b]);
    __syncthreads();

    #pragma unroll
    for (int b = 0; b < B; b++) a[b] = lb2[t];
    for (int k = 0; k < DL; k++) {
        float w = lw2[k * DL + t];
        #pragma unroll
        for (int b = 0; b < B; b++) a[b] = fmaf(Hh[b * DL + k], w, a[b]);
    }
    #pragma unroll
    for (int b = 0; b < B; b++) out[b * DL + t] = a[b];
}

// -------- launch --------
extern "C" void kernel_launch(void* const* d_in, const int* in_sizes, int n_in,
                              void* d_out, int out_size) {
    const float* pos_emb  = (const float*)d_in[0];
    const float* pred_emb = (const float*)d_in[1];
    const float* role_emb = (const float*)d_in[2];
    const float* w1       = (const float*)d_in[3];
    const float* b1       = (const float*)d_in[4];
    const float* w2       = (const float*)d_in[5];
    const float* b2       = (const float*)d_in[6];
    const float* ln_g     = (const float*)d_in[7];
    const float* ln_b     = (const float*)d_in[8];
    const float* lw1      = (const float*)d_in[9];
    const float* lb1      = (const float*)d_in[10];
    const float* lw2      = (const float*)d_in[11];
    const float* lb2      = (const float*)d_in[12];
    const int* pred_idx   = (const int*)d_in[13];
    const int* a0         = (const int*)d_in[14];
    const int* a1         = (const int*)d_in[15];
    const int* role_idx   = (const int*)d_in[16];
    const int* is_role    = (const int*)d_in[17];
    const int* add_rev    = (const int*)d_in[18];
    const int* mask       = (const int*)d_in[19];
    float* out = (float*)d_out;

    // dynamic smem for the edge kernel (96 KB > 48 KB default)
    cudaFuncSetAttribute(edge_mlp_kernel,
                         cudaFuncAttributeMaxDynamicSharedMemorySize,
                         TE * K1 * (int)sizeof(float));

    zero_kernel<<<(B * S * D + 255) / 256, 256>>>();
    compact_kernel<<<(NE + 255) / 256, 256>>>(mask, is_role, add_rev);
    edge_mlp_kernel<<<(2 * NE + TE - 1) / TE, 256, TE * K1 * sizeof(float)>>>(
        pos_emb, pred_emb, role_emb, w1, b1, w2, b2,
        pred_idx, a0, a1, role_idx, is_role);
    dim3 g(S / 32, B);
    norm_pool_kernel<<<g, 256>>>(pos_emb, ln_g, ln_b);
    final_kernel<<<1, 256>>>(lw1, lb1, lw2, lb2, out);
}

// round 2
// speedup vs baseline: 1.0007x; 1.0007x over previous
#include <cuda_runtime.h>
#include <cuda_bf16.h>
#include <math.h>

// Problem constants (fixed shapes per reference)
#define D   256
#define DL  256
#define S   2048
#define B   8
#define F   8192
#define NE  (B * F)        // 65536 edges
#define K1  (3 * D)        // 768  (concat input)
#define H1  (2 * D)        // 512  (hidden)
#define TE  32             // edges per tile in edge_mlp

// -------- device scratch (no allocations allowed) --------
__device__ float g_agg[B * S * D];     // 16 MB accumulator
__device__ float g_pooled[B * D];      // pooled sums
__device__ int   g_items[2 * NE];      // compacted (edge,dir) work items
__device__ int   g_count;

__device__ __forceinline__ float gelu_exact(float x) {
    // exact GELU: x * Phi(x)
    return x * normcdff(x);
}

// -------- kernel 1: zero scratch --------
__global__ void zero_kernel() {
    int i = blockIdx.x * blockDim.x + threadIdx.x;
    if (i < B * S * D) g_agg[i] = 0.0f;
    if (i < B * D)     g_pooled[i] = 0.0f;
    if (i == 0)        g_count = 0;
}

// -------- kernel 2: compact work items --------
// fwd item for every valid edge; rev item when valid & !role & add_rev
__global__ void compact_kernel(const int* __restrict__ mask,
                               const int* __restrict__ is_role,
                               const int* __restrict__ add_rev) {
    int e = blockIdx.x * blockDim.x + threadIdx.x;
    if (e >= NE) return;
    if (!mask[e]) return;
    bool rev = (!is_role[e]) && add_rev[e];
    int slot = atomicAdd(&g_count, rev ? 2 : 1);
    g_items[slot] = e << 1;                  // fwd
    if (rev) g_items[slot + 1] = (e << 1) | 1;  // rev
}

// -------- kernel 3: edge MLP + scatter --------
// One CTA handles TE work items: gather X[TE][768] into smem,
// layer1 (768->512) + exact gelu, layer2 (512->256), atomic scatter.
__global__ __launch_bounds__(256) void edge_mlp_kernel(
    const float* __restrict__ pos,   // pos_emb (nodes = first S rows)
    const float* __restrict__ pred,  // pred_emb
    const float* __restrict__ role,  // role_emb
    const float* __restrict__ w1, const float* __restrict__ b1,
    const float* __restrict__ w2, const float* __restrict__ b2,
    const int* __restrict__ pred_idx,
    const int* __restrict__ a0, const int* __restrict__ a1,
    const int* __restrict__ role_idx, const int* __restrict__ is_role)
{
    extern __shared__ float sm[];            // TE*K1 floats (X), reused as H (TE*H1)
    __shared__ const float* srcp[TE][3];
    __shared__ int stgt[TE];                 // (b*S + tgt)*D

    int t = threadIdx.x;                     // 256 threads
    int base = blockIdx.x * TE;
    int count = g_count;
    if (base >= count) return;
    int nE = min(TE, count - base);

    if (t < nE) {
        int item = g_items[base + t];
        int e   = item >> 1;
        int dir = item & 1;
        int b   = e >> 13;                   // F = 8192 = 2^13
        int i0 = a0[e], i1 = a1[e];
        int pi = pred_idx[e];
        const float* s0;
        const float* s2;
        int tg;
        if (dir == 0) {
            int r = is_role[e];
            s0 = pos + (size_t)i0 * D;
            s2 = r ? (role + (size_t)role_idx[e] * D) : (pos + (size_t)i1 * D);
            tg = r ? i0 : i1;
        } else {
            s0 = pos + (size_t)i1 * D;
            s2 = pos + (size_t)i0 * D;
            tg = i0;
        }
        srcp[t][0] = s0;
        srcp[t][1] = pred + (size_t)pi * D;
        srcp[t][2] = s2;
        stgt[t] = (b * S + tg) * D;
    }
    __syncthreads();

    // gather: 3 segments of 256 floats per edge, coalesced
    for (int e = 0; e < nE; e++) {
        sm[e * K1 +       t] = srcp[e][0][t];
        sm[e * K1 + 256 + t] = srcp[e][1][t];
        sm[e * K1 + 512 + t] = srcp[e][2][t];
    }
    __syncthreads();

    // ---- layer 1: H[e][j] = gelu(sum_k X[e][k] * w1[k][j] + b1[j]) ----
    // thread t owns j = 2t, 2t+1 for all TE edges
    float acc0[TE], acc1[TE];
    #pragma unroll
    for (int e = 0; e < TE; e++) { acc0[e] = 0.0f; acc1[e] = 0.0f; }

    const float2* w1v = (const float2*)w1;   // row k = 256 float2
    #pragma unroll 2
    for (int k = 0; k < K1; k++) {
        float2 w = __ldg(&w1v[(size_t)k * 256 + t]);
        #pragma unroll
        for (int e = 0; e < TE; e++) {
            float x = sm[e * K1 + k];        // broadcast
            acc0[e] = fmaf(x, w.x, acc0[e]);
            acc1[e] = fmaf(x, w.y, acc1[e]);
        }
    }
    float2 bj = ((const float2*)b1)[t];
    __syncthreads();                          // done reading X; reuse smem for H

    float2* Hs2 = (float2*)sm;                // row e = 256 float2
    #pragma unroll
    for (int e = 0; e < TE; e++) {
        float2 h;
        h.x = gelu_exact(acc0[e] + bj.x);
        h.y = gelu_exact(acc1[e] + bj.y);
        Hs2[e * 256 + t] = h;
    }
    __syncthreads();

    // ---- layer 2: msg[e][d] = sum_k H[e][k] * w2[k][d] + b2[d], d = t ----
    float acc2[TE];
    #pragma unroll
    for (int e = 0; e < TE; e++) acc2[e] = 0.0f;

    const float* Hs = sm;
    #pragma unroll 2
    for (int k = 0; k < H1; k++) {
        float w = __ldg(&w2[(size_t)k * D + t]);
        #pragma unroll
        for (int e = 0; e < TE; e++) {
            acc2[e] = fmaf(Hs[e * H1 + k], w, acc2[e]);
        }
    }
    float bb = b2[t];
    for (int e = 0; e < nE; e++) {
        atomicAdd(&g_agg[stgt[e] + t], acc2[e] + bb);
    }
}

// -------- kernel 4: x = nodes + agg, layernorm, pooled mean --------
// grid (S/32, B), 256 threads; warp per row, 4 rows per warp
__global__ void norm_pool_kernel(const float* __restrict__ pos,
                                 const float* __restrict__ ln_g,
                                 const float* __restrict__ ln_b)
{
    int b = blockIdx.y;
    int s_base = blockIdx.x * 32;
    int warp = threadIdx.x >> 5;
    int lane = threadIdx.x & 31;

    float gg[8], be[8], pacc[8];
    #pragma unroll
    for (int i = 0; i < 8; i++) {
        gg[i] = ln_g[i * 32 + lane];
        be[i] = ln_b[i * 32 + lane];
        pacc[i] = 0.0f;
    }

    for (int r = warp; r < 32; r += 8) {
        int s = s_base + r;
        const float* ag = &g_agg[((size_t)b * S + s) * D];
        const float* ps = &pos[(size_t)s * D];
        float x[8];
        float sum = 0.0f;
        #pragma unroll
        for (int i = 0; i < 8; i++) {
            x[i] = ps[i * 32 + lane] + ag[i * 32 + lane];
            sum += x[i];
        }
        #pragma unroll
        for (int off = 16; off > 0; off >>= 1)
            sum += __shfl_xor_sync(0xFFFFFFFFu, sum, off);
        float mu = sum * (1.0f / D);
        float v = 0.0f;
        #pragma unroll
        for (int i = 0; i < 8; i++) { x[i] -= mu; v += x[i] * x[i]; }
        #pragma unroll
        for (int off = 16; off > 0; off >>= 1)
            v += __shfl_xor_sync(0xFFFFFFFFu, v, off);
        float inv = rsqrtf(v * (1.0f / D) + 1e-5f);
        #pragma unroll
        for (int i = 0; i < 8; i++)
            pacc[i] += x[i] * inv * gg[i] + be[i];
    }

    __shared__ float sp[256];
    sp[threadIdx.x] = 0.0f;
    __syncthreads();
    #pragma unroll
    for (int i = 0; i < 8; i++)
        atomicAdd(&sp[i * 32 + lane], pacc[i]);
    __syncthreads();
    int t = threadIdx.x;
    atomicAdd(&g_pooled[b * D + t], sp[t] * (1.0f / S));
}

// -------- kernel 5: final small MLP --------
__global__ void final_kernel(const float* __restrict__ lw1, const float* __restrict__ lb1,
                             const float* __restrict__ lw2, const float* __restrict__ lb2,
                             float* __restrict__ out)
{
    __shared__ float P[B * D];
    __shared__ float Hh[B * DL];
    int t = threadIdx.x;  // 256
    for (int i = t; i < B * D; i += 256) P[i] = g_pooled[i];
    __syncthreads();

    float a[B];
    #pragma unroll
    for (int b = 0; b < B; b++) a[b] = lb1[t];
    for (int k = 0; k < D; k++) {
        float w = lw1[k * DL + t];
        #pragma unroll
        for (int b = 0; b < B; b++) a[b] = fmaf(P[b * D + k], w, a[b]);
    }
    #pragma unroll
    for (int b = 0; b < B; b++) Hh[b * DL + t] = gelu_exact(a[b]);
    __syncthreads();

    #pragma unroll
    for (int b = 0; b < B; b++) a[b] = lb2[t];
    for (int k = 0; k < DL; k++) {
        float w = lw2[k * DL + t];
        #pragma unroll
        for (int b = 0; b < B; b++) a[b] = fmaf(Hh[b * DL + k], w, a[b]);
    }
    #pragma unroll
    for (int b = 0; b < B; b++) out[b * DL + t] = a[b];
}

// -------- launch --------
extern "C" void kernel_launch(void* const* d_in, const int* in_sizes, int n_in,
                              void* d_out, int out_size) {
    const float* pos_emb  = (const float*)d_in[0];
    const float* pred_emb = (const float*)d_in[1];
    const float* role_emb = (const float*)d_in[2];
    const float* w1       = (const float*)d_in[3];
    const float* b1       = (const float*)d_in[4];
    const float* w2       = (const float*)d_in[5];
    const float* b2       = (const float*)d_in[6];
    const float* ln_g     = (const float*)d_in[7];
    const float* ln_b     = (const float*)d_in[8];
    const float* lw1      = (const float*)d_in[9];
    const float* lb1      = (const float*)d_in[10];
    const float* lw2      = (const float*)d_in[11];
    const float* lb2      = (const float*)d_in[12];
    const int* pred_idx   = (const int*)d_in[13];
    const int* a0         = (const int*)d_in[14];
    const int* a1         = (const int*)d_in[15];
    const int* role_idx   = (const int*)d_in[16];
    const int* is_role    = (const int*)d_in[17];
    const int* add_rev    = (const int*)d_in[18];
    const int* mask       = (const int*)d_in[19];
    float* out = (float*)d_out;

    // dynamic smem for the edge kernel (96 KB > 48 KB default)
    cudaFuncSetAttribute(edge_mlp_kernel,
                         cudaFuncAttributeMaxDynamicSharedMemorySize,
                         TE * K1 * (int)sizeof(float));

    zero_kernel<<<(B * S * D + 255) / 256, 256>>>();
    compact_kernel<<<(NE + 255) / 256, 256>>>(mask, is_role, add_rev);
    edge_mlp_kernel<<<(2 * NE + TE - 1) / TE, 256, TE * K1 * sizeof(float)>>>(
        pos_emb, pred_emb, role_emb, w1, b1, w2, b2,
        pred_idx, a0, a1, role_idx, is_role);
    dim3 g(S / 32, B);
    norm_pool_kernel<<<g, 256>>>(pos_emb, ln_g, ln_b);
    final_kernel<<<1, 256>>>(lw1, lb1, lw2, lb2, out);
}

// round 7
// speedup vs baseline: 2.9708x; 2.9686x over previous
#include <cuda_runtime.h>
#include <cuda_bf16.h>
#include <math.h>
#include <stdint.h>

#define D    256
#define DL   256
#define S    2048
#define B    8
#define F    8192
#define NE   (B * F)
#define MAXIT (2 * NE)          // 131072 max work items
#define TAB_PRED 2048
#define TAB_ROLE 3072
#define TAB_ROWS 3138
#define STAGE_PITCH 260
#define DYN_SMEM (128 * STAGE_PITCH * 4)   // 133120 >= 110592 compute region

// ---------------- device scratch ----------------
__device__ float g_agg[B * S * D];
__device__ float g_pooled[B * D];
__device__ int   g_items[MAXIT];
__device__ int   g_count;
__device__ __align__(16) __nv_bfloat16 g_tabh[TAB_ROWS * 256];
__device__ __align__(16) __nv_bfloat16 g_tabl[TAB_ROWS * 256];
__device__ __align__(16) __nv_bfloat16 g_w1th[512 * 768];   // W1^T [n][k]
__device__ __align__(16) __nv_bfloat16 g_w1tl[512 * 768];
__device__ __align__(16) __nv_bfloat16 g_w2th[256 * 512];   // W2^T [n][k]
__device__ __align__(16) __nv_bfloat16 g_w2tl[256 * 512];
__device__ __align__(16) __nv_bfloat16 g_Hh[(size_t)MAXIT * 512];
__device__ __align__(16) __nv_bfloat16 g_Hl[(size_t)MAXIT * 512];

__device__ __forceinline__ uint32_t smem_u32_of(const void* p) {
    uint32_t a;
    asm("{ .reg .u64 t; cvta.to.shared.u64 t, %1; cvt.u32.u64 %0, t; }" : "=r"(a) : "l"(p));
    return a;
}
__device__ __forceinline__ float gelu_e(float x) { return x * normcdff(x); }

#define LDSM4(r0, r1, r2, r3, addr) \
    asm volatile("ldmatrix.sync.aligned.m8n8.x4.shared.b16 {%0,%1,%2,%3}, [%4];" \
        : "=r"(r0), "=r"(r1), "=r"(r2), "=r"(r3) : "r"(addr))

#define MMA16816(c, a, b0, b1) \
    asm volatile("mma.sync.aligned.m16n8k16.row.col.f32.bf16.bf16.f32 " \
        "{%0,%1,%2,%3}, {%4,%5,%6,%7}, {%8,%9}, {%0,%1,%2,%3};" \
        : "+f"((c)[0]), "+f"((c)[1]), "+f"((c)[2]), "+f"((c)[3]) \
        : "r"((a)[0]), "r"((a)[1]), "r"((a)[2]), "r"((a)[3]), "r"(b0), "r"(b1))

// ---------------- kernel: zero scratch ----------------
__global__ void zero_kernel() {
    int i = blockIdx.x * blockDim.x + threadIdx.x;
    if (i < B * S * D) g_agg[i] = 0.0f;
    if (i < B * D)     g_pooled[i] = 0.0f;
    if (i == 0)        g_count = 0;
}

// ---------------- kernel: compact work items ----------------
__global__ void compact_kernel(const int* __restrict__ mask, const int* __restrict__ is_role,
                               const int* __restrict__ add_rev) {
    int e = blockIdx.x * blockDim.x + threadIdx.x;
    if (e >= NE) return;
    if (!mask[e]) return;
    bool rev = (!is_role[e]) && add_rev[e];
    int slot = atomicAdd(&g_count, rev ? 2 : 1);
    g_items[slot] = e << 1;
    if (rev) g_items[slot + 1] = (e << 1) | 1;
}

// ---------------- kernel: split tables + transposed weights to bf16 hi/lo ----------------
__global__ void prep_kernel(const float* __restrict__ pos, const float* __restrict__ pred,
                            const float* __restrict__ role,
                            const float* __restrict__ w1, const float* __restrict__ w2) {
    int tid = blockIdx.x * blockDim.x + threadIdx.x;
    const int NTAB = TAB_ROWS * 256;          // 803328
    const int NW1 = 512 * 768;                // 393216
    const int NW2 = 256 * 512;                // 131072
    if (tid < NTAB) {
        int row = tid >> 8, col = tid & 255;
        float v;
        if (row < TAB_PRED)      v = pos[tid];
        else if (row < TAB_ROLE) v = pred[(row - TAB_PRED) * 256 + col];
        else                     v = role[(row - TAB_ROLE) * 256 + col];
        __nv_bfloat16 h = __float2bfloat16(v);
        g_tabh[tid] = h;
        g_tabl[tid] = __float2bfloat16(v - __bfloat162float(h));
    } else if (tid < NTAB + NW1) {
        int u = tid - NTAB;                    // u = n*768 + k
        int n = u / 768, k = u - n * 768;
        float v = w1[(size_t)k * 512 + n];
        __nv_bfloat16 h = __float2bfloat16(v);
        g_w1th[u] = h;
        g_w1tl[u] = __float2bfloat16(v - __bfloat162float(h));
    } else if (tid < NTAB + NW1 + NW2) {
        int u = tid - NTAB - NW1;              // u = n*512 + k
        int n = u / 512, k = u - n * 512;
        float v = w2[(size_t)k * 256 + n];
        __nv_bfloat16 h = __float2bfloat16(v);
        g_w2th[u] = h;
        g_w2tl[u] = __float2bfloat16(v - __bfloat162float(h));
    }
}

// ---------------- GEMM1: X[128x768] @ W1[768x512] -> gelu -> g_H ----------------
// grid = 1024 tiles x 2 n-halves. CTA 256 thr, warp tile 32(M) x 128(N).
__global__ void __launch_bounds__(256, 1)
gemm1_kernel(const int* __restrict__ pred_idx,
             const int* __restrict__ a0, const int* __restrict__ a1,
             const int* __restrict__ role_idx, const int* __restrict__ is_role,
             const float* __restrict__ b1) {
    extern __shared__ char smraw[];
    __shared__ int ssrc[128][3];

    int t = threadIdx.x;
    int tile = blockIdx.x >> 1, nh = blockIdx.x & 1;
    int count = g_count;
    int base = tile * 128;
    if (base >= count) return;
    int nE = min(128, count - base);

    if (t < 128) {
        int r0 = 0, r1 = TAB_PRED, r2 = 0;
        if (t < nE) {
            int item = g_items[base + t];
            int e = item >> 1, dir = item & 1;
            int i0 = a0[e], i1 = a1[e];
            r1 = TAB_PRED + pred_idx[e];
            if (dir == 0) {
                int rr = is_role[e];
                r0 = i0;
                r2 = rr ? (TAB_ROLE + role_idx[e]) : i1;
            } else { r0 = i1; r2 = i0; }
        }
        ssrc[t][0] = r0; ssrc[t][1] = r1; ssrc[t][2] = r2;
    }
    __syncthreads();

    uint32_t xh_u = smem_u32_of(smraw);
    uint32_t xl_u = xh_u + 18432;
    uint32_t wh_u = xh_u + 36864;
    uint32_t wl_u = xh_u + 73728;

    int w = t >> 5, lane = t & 31;
    int wm = w >> 1, wn = w & 1;
    int blk = lane >> 3, brow = lane & 7;

    float acc[128];
    #pragma unroll
    for (int i = 0; i < 128; i++) acc[i] = 0.0f;

    for (int kc = 0; kc < 12; kc++) {
        if (kc) __syncthreads();
        // gather X chunk [128 x 64] hi+lo (uint4 copies from split tables)
        {
            int seg = kc >> 2;
            int inner8 = (kc & 3) * 8;   // uint4 offset within 256-col row
            #pragma unroll
            for (int i = t; i < 2048; i += 256) {
                int half = i >> 10;
                int j = i & 1023;
                int e = j >> 3, q = j & 7;
                int row = ssrc[e][seg];
                const uint4* src4 = half ? (const uint4*)g_tabl : (const uint4*)g_tabh;
                ((uint4*)(smraw + half * 18432))[e * 9 + q] = src4[row * 32 + inner8 + q];
            }
        }
        // load W1^T chunk [256 n x 64 k] hi+lo
        {
            #pragma unroll
            for (int i = t; i < 4096; i += 256) {
                int half = i >> 11;
                int j = i & 2047;
                int r = j >> 3, q = j & 7;
                int gn = nh * 256 + r;
                const uint4* src4 = half ? (const uint4*)g_w1tl : (const uint4*)g_w1th;
                ((uint4*)(smraw + 36864 + half * 36864))[r * 9 + q] = src4[gn * 96 + kc * 8 + q];
            }
        }
        __syncthreads();

        #pragma unroll
        for (int kk = 0; kk < 4; kk++) {
            uint32_t ah[2][4], al[2][4];
            #pragma unroll
            for (int mf = 0; mf < 2; mf++) {
                uint32_t off = ((wm * 32 + mf * 16 + (blk & 1) * 8 + brow) * 72
                                + kk * 16 + (blk >> 1) * 8) * 2;
                LDSM4(ah[mf][0], ah[mf][1], ah[mf][2], ah[mf][3], xh_u + off);
                LDSM4(al[mf][0], al[mf][1], al[mf][2], al[mf][3], xl_u + off);
            }
            #pragma unroll
            for (int nf2 = 0; nf2 < 8; nf2++) {
                uint32_t boff = ((wn * 128 + nf2 * 16 + (blk >> 1) * 8 + brow) * 72
                                 + kk * 16 + (blk & 1) * 8) * 2;
                uint32_t bh[4], bl[4];
                LDSM4(bh[0], bh[1], bh[2], bh[3], wh_u + boff);
                LDSM4(bl[0], bl[1], bl[2], bl[3], wl_u + boff);
                float* c0 = &acc[(nf2 * 2) * 4];
                float* c1 = &acc[(nf2 * 2 + 1) * 4];
                float* c2 = &acc[(16 + nf2 * 2) * 4];
                float* c3 = &acc[(16 + nf2 * 2 + 1) * 4];
                MMA16816(c0, ah[0], bh[0], bh[1]);
                MMA16816(c1, ah[0], bh[2], bh[3]);
                MMA16816(c2, ah[1], bh[0], bh[1]);
                MMA16816(c3, ah[1], bh[2], bh[3]);
                MMA16816(c0, ah[0], bl[0], bl[1]);
                MMA16816(c1, ah[0], bl[2], bl[3]);
                MMA16816(c2, ah[1], bl[0], bl[1]);
                MMA16816(c3, ah[1], bl[2], bl[3]);
                MMA16816(c0, al[0], bh[0], bh[1]);
                MMA16816(c1, al[0], bh[2], bh[3]);
                MMA16816(c2, al[1], bh[0], bh[1]);
                MMA16816(c3, al[1], bh[2], bh[3]);
            }
        }
    }
    __syncthreads();

    // stage accumulators, then bias+gelu+split -> g_H
    float* stage = (float*)smraw;
    int g = lane >> 2, i2 = (lane & 3) * 2;
    #pragma unroll
    for (int mf = 0; mf < 2; mf++)
        #pragma unroll
        for (int nf = 0; nf < 16; nf++) {
            float* c = &acc[(mf * 16 + nf) * 4];
            int r = wm * 32 + mf * 16 + g;
            int col = wn * 128 + nf * 8 + i2;
            stage[r * STAGE_PITCH + col]     = c[0];
            stage[r * STAGE_PITCH + col + 1] = c[1];
            stage[(r + 8) * STAGE_PITCH + col]     = c[2];
            stage[(r + 8) * STAGE_PITCH + col + 1] = c[3];
        }
    __syncthreads();
    float bias = b1[nh * 256 + t];
    for (int e = 0; e < nE; e++) {
        float x = stage[e * STAGE_PITCH + t] + bias;
        float y = gelu_e(x);
        __nv_bfloat16 h = __float2bfloat16(y);
        size_t o = (size_t)(base + e) * 512 + nh * 256 + t;
        g_Hh[o] = h;
        g_Hl[o] = __float2bfloat16(y - __bfloat162float(h));
    }
}

// ---------------- GEMM2: H[128x512] @ W2[512x256] -> +b2 -> atomic scatter ----------------
__global__ void __launch_bounds__(256, 1)
gemm2_kernel(const int* __restrict__ a0, const int* __restrict__ a1,
             const int* __restrict__ is_role, const float* __restrict__ b2) {
    extern __shared__ char smraw[];
    __shared__ int stgt[128];

    int t = threadIdx.x;
    int tile = blockIdx.x;
    int count = g_count;
    int base = tile * 128;
    if (base >= count) return;
    int nE = min(128, count - base);

    if (t < 128) {
        int tg = 0, bidx = 0;
        if (t < nE) {
            int item = g_items[base + t];
            int e = item >> 1, dir = item & 1;
            bidx = e >> 13;
            int i0 = a0[e], i1 = a1[e];
            if (dir == 0) { int rr = is_role[e]; tg = rr ? i0 : i1; }
            else tg = i0;
        }
        stgt[t] = (bidx * S + tg) * D;
    }
    __syncthreads();

    uint32_t xh_u = smem_u32_of(smraw);
    uint32_t xl_u = xh_u + 18432;
    uint32_t wh_u = xh_u + 36864;
    uint32_t wl_u = xh_u + 73728;

    int w = t >> 5, lane = t & 31;
    int wm = w >> 1, wn = w & 1;
    int blk = lane >> 3, brow = lane & 7;

    float acc[128];
    #pragma unroll
    for (int i = 0; i < 128; i++) acc[i] = 0.0f;

    for (int kc = 0; kc < 8; kc++) {
        if (kc) __syncthreads();
        // load H chunk [128 x 64] hi+lo — fully coalesced (rows are consecutive items)
        {
            #pragma unroll
            for (int i = t; i < 2048; i += 256) {
                int half = i >> 10;
                int j = i & 1023;
                int e = j >> 3, q = j & 7;
                const uint4* src4 = half ? (const uint4*)g_Hl : (const uint4*)g_Hh;
                ((uint4*)(smraw + half * 18432))[e * 9 + q] =
                    src4[(size_t)(base + e) * 64 + kc * 8 + q];
            }
        }
        // load W2^T chunk [256 n x 64 k] hi+lo
        {
            #pragma unroll
            for (int i = t; i < 4096; i += 256) {
                int half = i >> 11;
                int j = i & 2047;
                int r = j >> 3, q = j & 7;
                const uint4* src4 = half ? (const uint4*)g_w2tl : (const uint4*)g_w2th;
                ((uint4*)(smraw + 36864 + half * 36864))[r * 9 + q] = src4[r * 64 + kc * 8 + q];
            }
        }
        __syncthreads();

        #pragma unroll
        for (int kk = 0; kk < 4; kk++) {
            uint32_t ah[2][4], al[2][4];
            #pragma unroll
            for (int mf = 0; mf < 2; mf++) {
                uint32_t off = ((wm * 32 + mf * 16 + (blk & 1) * 8 + brow) * 72
                                + kk * 16 + (blk >> 1) * 8) * 2;
                LDSM4(ah[mf][0], ah[mf][1], ah[mf][2], ah[mf][3], xh_u + off);
                LDSM4(al[mf][0], al[mf][1], al[mf][2], al[mf][3], xl_u + off);
            }
            #pragma unroll
            for (int nf2 = 0; nf2 < 8; nf2++) {
                uint32_t boff = ((wn * 128 + nf2 * 16 + (blk >> 1) * 8 + brow) * 72
                                 + kk * 16 + (blk & 1) * 8) * 2;
                uint32_t bh[4], bl[4];
                LDSM4(bh[0], bh[1], bh[2], bh[3], wh_u + boff);
                LDSM4(bl[0], bl[1], bl[2], bl[3], wl_u + boff);
                float* c0 = &acc[(nf2 * 2) * 4];
                float* c1 = &acc[(nf2 * 2 + 1) * 4];
                float* c2 = &acc[(16 + nf2 * 2) * 4];
                float* c3 = &acc[(16 + nf2 * 2 + 1) * 4];
                MMA16816(c0, ah[0], bh[0], bh[1]);
                MMA16816(c1, ah[0], bh[2], bh[3]);
                MMA16816(c2, ah[1], bh[0], bh[1]);
                MMA16816(c3, ah[1], bh[2], bh[3]);
                MMA16816(c0, ah[0], bl[0], bl[1]);
                MMA16816(c1, ah[0], bl[2], bl[3]);
                MMA16816(c2, ah[1], bl[0], bl[1]);
                MMA16816(c3, ah[1], bl[2], bl[3]);
                MMA16816(c0, al[0], bh[0], bh[1]);
                MMA16816(c1, al[0], bh[2], bh[3]);
                MMA16816(c2, al[1], bh[0], bh[1]);
                MMA16816(c3, al[1], bh[2], bh[3]);
            }
        }
    }
    __syncthreads();

    float* stage = (float*)smraw;
    int g = lane >> 2, i2 = (lane & 3) * 2;
    #pragma unroll
    for (int mf = 0; mf < 2; mf++)
        #pragma unroll
        for (int nf = 0; nf < 16; nf++) {
            float* c = &acc[(mf * 16 + nf) * 4];
            int r = wm * 32 + mf * 16 + g;
            int col = wn * 128 + nf * 8 + i2;
            stage[r * STAGE_PITCH + col]     = c[0];
            stage[r * STAGE_PITCH + col + 1] = c[1];
            stage[(r + 8) * STAGE_PITCH + col]     = c[2];
            stage[(r + 8) * STAGE_PITCH + col + 1] = c[3];
        }
    __syncthreads();
    float bias = b2[t];
    for (int e = 0; e < nE; e++)
        atomicAdd(&g_agg[stgt[e] + t], stage[e * STAGE_PITCH + t] + bias);
}

// ---------------- layernorm + pooled mean ----------------
__global__ void norm_pool_kernel(const float* __restrict__ pos,
                                 const float* __restrict__ ln_g,
                                 const float* __restrict__ ln_b) {
    int b = blockIdx.y;
    int s_base = blockIdx.x * 32;
    int warp = threadIdx.x >> 5, lane = threadIdx.x & 31;
    float gg[8], be[8], pacc[8];
    #pragma unroll
    for (int i = 0; i < 8; i++) {
        gg[i] = ln_g[i * 32 + lane]; be[i] = ln_b[i * 32 + lane]; pacc[i] = 0.0f;
    }
    for (int r = warp; r < 32; r += 8) {
        int ss = s_base + r;
        const float* ag = &g_agg[((size_t)b * S + ss) * D];
        const float* ps = &pos[(size_t)ss * D];
        float x[8]; float sum = 0.0f;
        #pragma unroll
        for (int i = 0; i < 8; i++) { x[i] = ps[i * 32 + lane] + ag[i * 32 + lane]; sum += x[i]; }
        #pragma unroll
        for (int off = 16; off > 0; off >>= 1) sum += __shfl_xor_sync(0xFFFFFFFFu, sum, off);
        float mu = sum * (1.0f / D); float v = 0.0f;
        #pragma unroll
        for (int i = 0; i < 8; i++) { x[i] -= mu; v += x[i] * x[i]; }
        #pragma unroll
        for (int off = 16; off > 0; off >>= 1) v += __shfl_xor_sync(0xFFFFFFFFu, v, off);
        float inv = rsqrtf(v * (1.0f / D) + 1e-5f);
        #pragma unroll
        for (int i = 0; i < 8; i++) pacc[i] += x[i] * inv * gg[i] + be[i];
    }
    __shared__ float sp[256];
    sp[threadIdx.x] = 0.0f;
    __syncthreads();
    #pragma unroll
    for (int i = 0; i < 8; i++) atomicAdd(&sp[i * 32 + lane], pacc[i]);
    __syncthreads();
    atomicAdd(&g_pooled[b * D + threadIdx.x], sp[threadIdx.x] * (1.0f / S));
}

// ---------------- final small MLP ----------------
__global__ void final_kernel(const float* __restrict__ lw1, const float* __restrict__ lb1,
                             const float* __restrict__ lw2, const float* __restrict__ lb2,
                             float* __restrict__ out) {
    __shared__ float P[B * D];
    __shared__ float Hh[B * DL];
    int t = threadIdx.x;
    for (int i = t; i < B * D; i += 256) P[i] = g_pooled[i];
    __syncthreads();
    float a[B];
    #pragma unroll
    for (int b = 0; b < B; b++) a[b] = lb1[t];
    for (int k = 0; k < D; k++) {
        float wv = lw1[k * DL + t];
        #pragma unroll
        for (int b = 0; b < B; b++) a[b] = fmaf(P[b * D + k], wv, a[b]);
    }
    #pragma unroll
    for (int b = 0; b < B; b++) Hh[b * DL + t] = gelu_e(a[b]);
    __syncthreads();
    #pragma unroll
    for (int b = 0; b < B; b++) a[b] = lb2[t];
    for (int k = 0; k < DL; k++) {
        float wv = lw2[k * DL + t];
        #pragma unroll
        for (int b = 0; b < B; b++) a[b] = fmaf(Hh[b * DL + k], wv, a[b]);
    }
    #pragma unroll
    for (int b = 0; b < B; b++) out[b * DL + t] = a[b];
}

// ---------------- launch ----------------
extern "C" void kernel_launch(void* const* d_in, const int* in_sizes, int n_in,
                              void* d_out, int out_size) {
    const float* pos_emb  = (const float*)d_in[0];
    const float* pred_emb = (const float*)d_in[1];
    const float* role_emb = (const float*)d_in[2];
    const float* w1       = (const float*)d_in[3];
    const float* b1       = (const float*)d_in[4];
    const float* w2       = (const float*)d_in[5];
    const float* b2       = (const float*)d_in[6];
    const float* ln_g     = (const float*)d_in[7];
    const float* ln_b     = (const float*)d_in[8];
    const float* lw1      = (const float*)d_in[9];
    const float* lb1      = (const float*)d_in[10];
    const float* lw2      = (const float*)d_in[11];
    const float* lb2      = (const float*)d_in[12];
    const int* pred_idx   = (const int*)d_in[13];
    const int* a0         = (const int*)d_in[14];
    const int* a1         = (const int*)d_in[15];
    const int* role_idx   = (const int*)d_in[16];
    const int* is_role    = (const int*)d_in[17];
    const int* add_rev    = (const int*)d_in[18];
    const int* mask       = (const int*)d_in[19];
    float* out = (float*)d_out;

    cudaFuncSetAttribute(gemm1_kernel, cudaFuncAttributeMaxDynamicSharedMemorySize, DYN_SMEM);
    cudaFuncSetAttribute(gemm2_kernel, cudaFuncAttributeMaxDynamicSharedMemorySize, DYN_SMEM);

    zero_kernel<<<(B * S * D + 255) / 256, 256>>>();
    compact_kernel<<<(NE + 255) / 256, 256>>>(mask, is_role, add_rev);
    {
        int total = TAB_ROWS * 256 + 512 * 768 + 256 * 512;
        prep_kernel<<<(total + 255) / 256, 256>>>(pos_emb, pred_emb, role_emb, w1, w2);
    }
    gemm1_kernel<<<(MAXIT / 128) * 2, 256, DYN_SMEM>>>(pred_idx, a0, a1, role_idx, is_role, b1);
    gemm2_kernel<<<MAXIT / 128, 256, DYN_SMEM>>>(a0, a1, is_role, b2);
    dim3 g(S / 32, B);
    norm_pool_kernel<<<g, 256>>>(pos_emb, ln_g, ln_b);
    final_kernel<<<1, 256>>>(lw1, lb1, lw2, lb2, out);
}

// round 8
// speedup vs baseline: 3.7382x; 1.2583x over previous
#include <cuda_runtime.h>
#include <cuda_bf16.h>
#include <math.h>
#include <stdint.h>

#define D    256
#define DL   256
#define S    2048
#define B    8
#define F    8192
#define NE   (B * F)
#define MAXIT (2 * NE)
#define TAB_PRED 2048
#define TAB_ROLE 3072
#define TAB_ROWS 3138
#define STAGE_PITCH 132
#define DYN_SMEM 73728   // X(hi/lo) 36864 + W(hi/lo) 36864 ; stage 128*132*4=67584 fits

// ---------------- device scratch ----------------
__device__ float g_agg[B * S * D];
__device__ float g_pooled[B * D];
__device__ int   g_items[MAXIT];
__device__ int   g_count;
__device__ __align__(16) __nv_bfloat16 g_tabh[TAB_ROWS * 256];
__device__ __align__(16) __nv_bfloat16 g_tabl[TAB_ROWS * 256];
__device__ __align__(16) __nv_bfloat16 g_w1th[512 * 768];   // W1^T [n][k]
__device__ __align__(16) __nv_bfloat16 g_w1tl[512 * 768];
__device__ __align__(16) __nv_bfloat16 g_w2th[256 * 512];   // W2^T [n][k]
__device__ __align__(16) __nv_bfloat16 g_w2tl[256 * 512];
__device__ __align__(16) __nv_bfloat16 g_Hh[(size_t)MAXIT * 512];
__device__ __align__(16) __nv_bfloat16 g_Hl[(size_t)MAXIT * 512];

__device__ __forceinline__ uint32_t smem_u32_of(const void* p) {
    uint32_t a;
    asm("{ .reg .u64 t; cvta.to.shared.u64 t, %1; cvt.u32.u64 %0, t; }" : "=r"(a) : "l"(p));
    return a;
}
__device__ __forceinline__ float gelu_e(float x) { return x * normcdff(x); }

#define LDSM4(r0, r1, r2, r3, addr) \
    asm volatile("ldmatrix.sync.aligned.m8n8.x4.shared.b16 {%0,%1,%2,%3}, [%4];" \
        : "=r"(r0), "=r"(r1), "=r"(r2), "=r"(r3) : "r"(addr))

#define MMA16816(c, a, b0, b1) \
    asm volatile("mma.sync.aligned.m16n8k16.row.col.f32.bf16.bf16.f32 " \
        "{%0,%1,%2,%3}, {%4,%5,%6,%7}, {%8,%9}, {%0,%1,%2,%3};" \
        : "+f"((c)[0]), "+f"((c)[1]), "+f"((c)[2]), "+f"((c)[3]) \
        : "r"((a)[0]), "r"((a)[1]), "r"((a)[2]), "r"((a)[3]), "r"(b0), "r"(b1))

// ---------------- zero ----------------
__global__ void zero_kernel() {
    int i = blockIdx.x * blockDim.x + threadIdx.x;
    if (i < B * S * D) g_agg[i] = 0.0f;
    if (i < B * D)     g_pooled[i] = 0.0f;
    if (i == 0)        g_count = 0;
}

// ---------------- compact ----------------
__global__ void compact_kernel(const int* __restrict__ mask, const int* __restrict__ is_role,
                               const int* __restrict__ add_rev) {
    int e = blockIdx.x * blockDim.x + threadIdx.x;
    if (e >= NE) return;
    if (!mask[e]) return;
    bool rev = (!is_role[e]) && add_rev[e];
    int slot = atomicAdd(&g_count, rev ? 2 : 1);
    g_items[slot] = e << 1;
    if (rev) g_items[slot + 1] = (e << 1) | 1;
}

// ---------------- prep: split tables + W^T hi/lo ----------------
__global__ void prep_kernel(const float* __restrict__ pos, const float* __restrict__ pred,
                            const float* __restrict__ role,
                            const float* __restrict__ w1, const float* __restrict__ w2) {
    int tid = blockIdx.x * blockDim.x + threadIdx.x;
    const int NTAB = TAB_ROWS * 256;
    const int NW1 = 512 * 768;
    const int NW2 = 256 * 512;
    if (tid < NTAB) {
        int row = tid >> 8, col = tid & 255;
        float v;
        if (row < TAB_PRED)      v = pos[tid];
        else if (row < TAB_ROLE) v = pred[(row - TAB_PRED) * 256 + col];
        else                     v = role[(row - TAB_ROLE) * 256 + col];
        __nv_bfloat16 h = __float2bfloat16(v);
        g_tabh[tid] = h;
        g_tabl[tid] = __float2bfloat16(v - __bfloat162float(h));
    } else if (tid < NTAB + NW1) {
        int u = tid - NTAB;                    // u = n*768 + k
        int n = u / 768, k = u - n * 768;
        float v = w1[(size_t)k * 512 + n];
        __nv_bfloat16 h = __float2bfloat16(v);
        g_w1th[u] = h;
        g_w1tl[u] = __float2bfloat16(v - __bfloat162float(h));
    } else if (tid < NTAB + NW1 + NW2) {
        int u = tid - NTAB - NW1;              // u = n*512 + k
        int n = u / 512, k = u - n * 512;
        float v = w2[(size_t)k * 256 + n];
        __nv_bfloat16 h = __float2bfloat16(v);
        g_w2th[u] = h;
        g_w2tl[u] = __float2bfloat16(v - __bfloat162float(h));
    }
}

// ---------------- GEMM1: X[128x768] @ W1[768x512] -> gelu -> g_H ----------------
// grid = tiles x 4 n-quarters; CTA 256 thr (8 warps), warp tile 32(M) x 64(N)
__global__ void __launch_bounds__(256, 2)
gemm1_kernel(const int* __restrict__ pred_idx,
             const int* __restrict__ a0, const int* __restrict__ a1,
             const int* __restrict__ role_idx, const int* __restrict__ is_role,
             const float* __restrict__ b1) {
    extern __shared__ char smraw[];
    __shared__ int ssrc[128][3];

    int t = threadIdx.x;
    int tile = blockIdx.x >> 2, nq = blockIdx.x & 3;
    int count = g_count;
    int base = tile * 128;
    if (base >= count) return;
    int nE = min(128, count - base);

    if (t < 128) {
        int r0 = 0, r1 = TAB_PRED, r2 = 0;
        if (t < nE) {
            int item = g_items[base + t];
            int e = item >> 1, dir = item & 1;
            int i0 = a0[e], i1 = a1[e];
            r1 = TAB_PRED + pred_idx[e];
            if (dir == 0) {
                int rr = is_role[e];
                r0 = i0;
                r2 = rr ? (TAB_ROLE + role_idx[e]) : i1;
            } else { r0 = i1; r2 = i0; }
        }
        ssrc[t][0] = r0; ssrc[t][1] = r1; ssrc[t][2] = r2;
    }
    __syncthreads();

    uint32_t xh_u = smem_u32_of(smraw);
    uint32_t xl_u = xh_u + 18432;
    uint32_t wh_u = xh_u + 36864;
    uint32_t wl_u = xh_u + 55296;

    int w = t >> 5, lane = t & 31;
    int wm = w >> 1, wn = w & 1;       // wm 0..3 (M), wn 0..1 (N 64-half)
    int blk = lane >> 3, brow = lane & 7;

    float acc[64];
    #pragma unroll
    for (int i = 0; i < 64; i++) acc[i] = 0.0f;

    for (int kc = 0; kc < 12; kc++) {
        if (kc) __syncthreads();
        // gather X chunk [128 x 64] hi+lo
        {
            int seg = kc >> 2;
            int inner8 = (kc & 3) * 8;
            #pragma unroll
            for (int i = t; i < 2048; i += 256) {
                int half = i >> 10;
                int j = i & 1023;
                int e = j >> 3, q = j & 7;
                int row = ssrc[e][seg];
                const uint4* src4 = half ? (const uint4*)g_tabl : (const uint4*)g_tabh;
                ((uint4*)(smraw + half * 18432))[e * 9 + q] = src4[row * 32 + inner8 + q];
            }
        }
        // load W1^T chunk [128 n x 64 k] hi+lo (n-quarter nq)
        {
            #pragma unroll
            for (int i = t; i < 2048; i += 256) {
                int half = i >> 10;
                int j = i & 1023;
                int r = j >> 3, q = j & 7;
                int gn = nq * 128 + r;
                const uint4* src4 = half ? (const uint4*)g_w1tl : (const uint4*)g_w1th;
                ((uint4*)(smraw + 36864 + half * 18432))[r * 9 + q] = src4[gn * 96 + kc * 8 + q];
            }
        }
        __syncthreads();

        #pragma unroll
        for (int kk = 0; kk < 4; kk++) {
            uint32_t ah[2][4], al[2][4];
            #pragma unroll
            for (int mf = 0; mf < 2; mf++) {
                uint32_t off = ((wm * 32 + mf * 16 + (blk & 1) * 8 + brow) * 72
                                + kk * 16 + (blk >> 1) * 8) * 2;
                LDSM4(ah[mf][0], ah[mf][1], ah[mf][2], ah[mf][3], xh_u + off);
                LDSM4(al[mf][0], al[mf][1], al[mf][2], al[mf][3], xl_u + off);
            }
            #pragma unroll
            for (int nf2 = 0; nf2 < 4; nf2++) {
                uint32_t boff = ((wn * 64 + nf2 * 16 + (blk >> 1) * 8 + brow) * 72
                                 + kk * 16 + (blk & 1) * 8) * 2;
                uint32_t bh[4], bl[4];
                LDSM4(bh[0], bh[1], bh[2], bh[3], wh_u + boff);
                LDSM4(bl[0], bl[1], bl[2], bl[3], wl_u + boff);
                float* c0 = &acc[(nf2 * 2) * 4];
                float* c1 = &acc[(nf2 * 2 + 1) * 4];
                float* c2 = &acc[(8 + nf2 * 2) * 4];
                float* c3 = &acc[(8 + nf2 * 2 + 1) * 4];
                MMA16816(c0, ah[0], bh[0], bh[1]);
                MMA16816(c1, ah[0], bh[2], bh[3]);
                MMA16816(c2, ah[1], bh[0], bh[1]);
                MMA16816(c3, ah[1], bh[2], bh[3]);
                MMA16816(c0, ah[0], bl[0], bl[1]);
                MMA16816(c1, ah[0], bl[2], bl[3]);
                MMA16816(c2, ah[1], bl[0], bl[1]);
                MMA16816(c3, ah[1], bl[2], bl[3]);
                MMA16816(c0, al[0], bh[0], bh[1]);
                MMA16816(c1, al[0], bh[2], bh[3]);
                MMA16816(c2, al[1], bh[0], bh[1]);
                MMA16816(c3, al[1], bh[2], bh[3]);
            }
        }
    }
    __syncthreads();

    // stage accumulators -> bias+gelu+split -> g_H
    float* stage = (float*)smraw;
    int g = lane >> 2, i2 = (lane & 3) * 2;
    #pragma unroll
    for (int mf = 0; mf < 2; mf++)
        #pragma unroll
        for (int nf = 0; nf < 8; nf++) {
            float* c = &acc[(mf * 8 + nf) * 4];
            int r = wm * 32 + mf * 16 + g;
            int col = wn * 64 + nf * 8 + i2;
            stage[r * STAGE_PITCH + col]     = c[0];
            stage[r * STAGE_PITCH + col + 1] = c[1];
            stage[(r + 8) * STAGE_PITCH + col]     = c[2];
            stage[(r + 8) * STAGE_PITCH + col + 1] = c[3];
        }
    __syncthreads();
    {
        int col = t & 127, eh = t >> 7;
        float bias = b1[nq * 128 + col];
        for (int e = eh; e < nE; e += 2) {
            float x = stage[e * STAGE_PITCH + col] + bias;
            float y = gelu_e(x);
            __nv_bfloat16 h = __float2bfloat16(y);
            size_t o = (size_t)(base + e) * 512 + nq * 128 + col;
            g_Hh[o] = h;
            g_Hl[o] = __float2bfloat16(y - __bfloat162float(h));
        }
    }
}

// ---------------- GEMM2: H[128x512] @ W2[512x256] -> +b2 -> atomic scatter ----------------
// grid = tiles x 2 n-halves; CTA 256 thr, warp tile 32x64
__global__ void __launch_bounds__(256, 2)
gemm2_kernel(const int* __restrict__ a0, const int* __restrict__ a1,
             const int* __restrict__ is_role, const float* __restrict__ b2) {
    extern __shared__ char smraw[];
    __shared__ int stgt[128];

    int t = threadIdx.x;
    int tile = blockIdx.x >> 1, nq = blockIdx.x & 1;
    int count = g_count;
    int base = tile * 128;
    if (base >= count) return;
    int nE = min(128, count - base);

    if (t < 128) {
        int tg = 0, bidx = 0;
        if (t < nE) {
            int item = g_items[base + t];
            int e = item >> 1, dir = item & 1;
            bidx = e >> 13;
            int i0 = a0[e], i1 = a1[e];
            if (dir == 0) { int rr = is_role[e]; tg = rr ? i0 : i1; }
            else tg = i0;
        }
        stgt[t] = (bidx * S + tg) * D;
    }
    __syncthreads();

    uint32_t xh_u = smem_u32_of(smraw);
    uint32_t xl_u = xh_u + 18432;
    uint32_t wh_u = xh_u + 36864;
    uint32_t wl_u = xh_u + 55296;

    int w = t >> 5, lane = t & 31;
    int wm = w >> 1, wn = w & 1;
    int blk = lane >> 3, brow = lane & 7;

    float acc[64];
    #pragma unroll
    for (int i = 0; i < 64; i++) acc[i] = 0.0f;

    for (int kc = 0; kc < 8; kc++) {
        if (kc) __syncthreads();
        // load H chunk [128 x 64] hi+lo (coalesced)
        {
            #pragma unroll
            for (int i = t; i < 2048; i += 256) {
                int half = i >> 10;
                int j = i & 1023;
                int e = j >> 3, q = j & 7;
                const uint4* src4 = half ? (const uint4*)g_Hl : (const uint4*)g_Hh;
                ((uint4*)(smraw + half * 18432))[e * 9 + q] =
                    src4[(size_t)(base + e) * 64 + kc * 8 + q];
            }
        }
        // load W2^T chunk [128 n x 64 k] hi+lo
        {
            #pragma unroll
            for (int i = t; i < 2048; i += 256) {
                int half = i >> 10;
                int j = i & 1023;
                int r = j >> 3, q = j & 7;
                int gn = nq * 128 + r;
                const uint4* src4 = half ? (const uint4*)g_w2tl : (const uint4*)g_w2th;
                ((uint4*)(smraw + 36864 + half * 18432))[r * 9 + q] = src4[gn * 64 + kc * 8 + q];
            }
        }
        __syncthreads();

        #pragma unroll
        for (int kk = 0; kk < 4; kk++) {
            uint32_t ah[2][4], al[2][4];
            #pragma unroll
            for (int mf = 0; mf < 2; mf++) {
                uint32_t off = ((wm * 32 + mf * 16 + (blk & 1) * 8 + brow) * 72
                                + kk * 16 + (blk >> 1) * 8) * 2;
                LDSM4(ah[mf][0], ah[mf][1], ah[mf][2], ah[mf][3], xh_u + off);
                LDSM4(al[mf][0], al[mf][1], al[mf][2], al[mf][3], xl_u + off);
            }
            #pragma unroll
            for (int nf2 = 0; nf2 < 4; nf2++) {
                uint32_t boff = ((wn * 64 + nf2 * 16 + (blk >> 1) * 8 + brow) * 72
                                 + kk * 16 + (blk & 1) * 8) * 2;
                uint32_t bh[4], bl[4];
                LDSM4(bh[0], bh[1], bh[2], bh[3], wh_u + boff);
                LDSM4(bl[0], bl[1], bl[2], bl[3], wl_u + boff);
                float* c0 = &acc[(nf2 * 2) * 4];
                float* c1 = &acc[(nf2 * 2 + 1) * 4];
                float* c2 = &acc[(8 + nf2 * 2) * 4];
                float* c3 = &acc[(8 + nf2 * 2 + 1) * 4];
                MMA16816(c0, ah[0], bh[0], bh[1]);
                MMA16816(c1, ah[0], bh[2], bh[3]);
                MMA16816(c2, ah[1], bh[0], bh[1]);
                MMA16816(c3, ah[1], bh[2], bh[3]);
                MMA16816(c0, ah[0], bl[0], bl[1]);
                MMA16816(c1, ah[0], bl[2], bl[3]);
                MMA16816(c2, ah[1], bl[0], bl[1]);
                MMA16816(c3, ah[1], bl[2], bl[3]);
                MMA16816(c0, al[0], bh[0], bh[1]);
                MMA16816(c1, al[0], bh[2], bh[3]);
                MMA16816(c2, al[1], bh[0], bh[1]);
                MMA16816(c3, al[1], bh[2], bh[3]);
            }
        }
    }
    __syncthreads();

    float* stage = (float*)smraw;
    int g = lane >> 2, i2 = (lane & 3) * 2;
    #pragma unroll
    for (int mf = 0; mf < 2; mf++)
        #pragma unroll
        for (int nf = 0; nf < 8; nf++) {
            float* c = &acc[(mf * 8 + nf) * 4];
            int r = wm * 32 + mf * 16 + g;
            int col = wn * 64 + nf * 8 + i2;
            stage[r * STAGE_PITCH + col]     = c[0];
            stage[r * STAGE_PITCH + col + 1] = c[1];
            stage[(r + 8) * STAGE_PITCH + col]     = c[2];
            stage[(r + 8) * STAGE_PITCH + col + 1] = c[3];
        }
    __syncthreads();
    {
        int col = t & 127, eh = t >> 7;
        float bias = b2[nq * 128 + col];
        for (int e = eh; e < nE; e += 2)
            atomicAdd(&g_agg[stgt[e] + nq * 128 + col],
                      stage[e * STAGE_PITCH + col] + bias);
    }
}

// ---------------- layernorm + pooled mean ----------------
__global__ void norm_pool_kernel(const float* __restrict__ pos,
                                 const float* __restrict__ ln_g,
                                 const float* __restrict__ ln_b) {
    int b = blockIdx.y;
    int s_base = blockIdx.x * 32;
    int warp = threadIdx.x >> 5, lane = threadIdx.x & 31;
    float gg[8], be[8], pacc[8];
    #pragma unroll
    for (int i = 0; i < 8; i++) {
        gg[i] = ln_g[i * 32 + lane]; be[i] = ln_b[i * 32 + lane]; pacc[i] = 0.0f;
    }
    for (int r = warp; r < 32; r += 8) {
        int ss = s_base + r;
        const float* ag = &g_agg[((size_t)b * S + ss) * D];
        const float* ps = &pos[(size_t)ss * D];
        float x[8]; float sum = 0.0f;
        #pragma unroll
        for (int i = 0; i < 8; i++) { x[i] = ps[i * 32 + lane] + ag[i * 32 + lane]; sum += x[i]; }
        #pragma unroll
        for (int off = 16; off > 0; off >>= 1) sum += __shfl_xor_sync(0xFFFFFFFFu, sum, off);
        float mu = sum * (1.0f / D); float v = 0.0f;
        #pragma unroll
        for (int i = 0; i < 8; i++) { x[i] -= mu; v += x[i] * x[i]; }
        #pragma unroll
        for (int off = 16; off > 0; off >>= 1) v += __shfl_xor_sync(0xFFFFFFFFu, v, off);
        float inv = rsqrtf(v * (1.0f / D) + 1e-5f);
        #pragma unroll
        for (int i = 0; i < 8; i++) pacc[i] += x[i] * inv * gg[i] + be[i];
    }
    __shared__ float sp[256];
    sp[threadIdx.x] = 0.0f;
    __syncthreads();
    #pragma unroll
    for (int i = 0; i < 8; i++) atomicAdd(&sp[i * 32 + lane], pacc[i]);
    __syncthreads();
    atomicAdd(&g_pooled[b * D + threadIdx.x], sp[threadIdx.x] * (1.0f / S));
}

// ---------------- final small MLP ----------------
__global__ void final_kernel(const float* __restrict__ lw1, const float* __restrict__ lb1,
                             const float* __restrict__ lw2, const float* __restrict__ lb2,
                             float* __restrict__ out) {
    __shared__ float P[B * D];
    __shared__ float Hh[B * DL];
    int t = threadIdx.x;
    for (int i = t; i < B * D; i += 256) P[i] = g_pooled[i];
    __syncthreads();
    float a[B];
    #pragma unroll
    for (int b = 0; b < B; b++) a[b] = lb1[t];
    for (int k = 0; k < D; k++) {
        float wv = lw1[k * DL + t];
        #pragma unroll
        for (int b = 0; b < B; b++) a[b] = fmaf(P[b * D + k], wv, a[b]);
    }
    #pragma unroll
    for (int b = 0; b < B; b++) Hh[b * DL + t] = gelu_e(a[b]);
    __syncthreads();
    #pragma unroll
    for (int b = 0; b < B; b++) a[b] = lb2[t];
    for (int k = 0; k < DL; k++) {
        float wv = lw2[k * DL + t];
        #pragma unroll
        for (int b = 0; b < B; b++) a[b] = fmaf(Hh[b * DL + k], wv, a[b]);
    }
    #pragma unroll
    for (int b = 0; b < B; b++) out[b * DL + t] = a[b];
}

// ---------------- launch ----------------
extern "C" void kernel_launch(void* const* d_in, const int* in_sizes, int n_in,
                              void* d_out, int out_size) {
    const float* pos_emb  = (const float*)d_in[0];
    const float* pred_emb = (const float*)d_in[1];
    const float* role_emb = (const float*)d_in[2];
    const float* w1       = (const float*)d_in[3];
    const float* b1       = (const float*)d_in[4];
    const float* w2       = (const float*)d_in[5];
    const float* b2       = (const float*)d_in[6];
    const float* ln_g     = (const float*)d_in[7];
    const float* ln_b     = (const float*)d_in[8];
    const float* lw1      = (const float*)d_in[9];
    const float* lb1      = (const float*)d_in[10];
    const float* lw2      = (const float*)d_in[11];
    const float* lb2      = (const float*)d_in[12];
    const int* pred_idx   = (const int*)d_in[13];
    const int* a0         = (const int*)d_in[14];
    const int* a1         = (const int*)d_in[15];
    const int* role_idx   = (const int*)d_in[16];
    const int* is_role    = (const int*)d_in[17];
    const int* add_rev    = (const int*)d_in[18];
    const int* mask       = (const int*)d_in[19];
    float* out = (float*)d_out;

    cudaFuncSetAttribute(gemm1_kernel, cudaFuncAttributeMaxDynamicSharedMemorySize, DYN_SMEM);
    cudaFuncSetAttribute(gemm2_kernel, cudaFuncAttributeMaxDynamicSharedMemorySize, DYN_SMEM);

    zero_kernel<<<(B * S * D + 255) / 256, 256>>>();
    compact_kernel<<<(NE + 255) / 256, 256>>>(mask, is_role, add_rev);
    {
        int total = TAB_ROWS * 256 + 512 * 768 + 256 * 512;
        prep_kernel<<<(total + 255) / 256, 256>>>(pos_emb, pred_emb, role_emb, w1, w2);
    }
    gemm1_kernel<<<(MAXIT / 128) * 4, 256, DYN_SMEM>>>(pred_idx, a0, a1, role_idx, is_role, b1);
    gemm2_kernel<<<(MAXIT / 128) * 2, 256, DYN_SMEM>>>(a0, a1, is_role, b2);
    dim3 g(S / 32, B);
    norm_pool_kernel<<<g, 256>>>(pos_emb, ln_g, ln_b);
    final_kernel<<<1, 256>>>(lw1, lb1, lw2, lb2, out);
}